// round 10
// baseline (speedup 1.0000x reference)
#include <cuda_runtime.h>
#include <cstdint>

// DepthwiseRREUp: groups=C*G conv_transpose2d, kernel=stride=2, pad=0.
// out[b,c,g, 2i+di, 2j+dj] = x[b,c,g,i,j] * rot90(dw[c], g)[di][dj]
//
// x:  [B=8, C=256, G=4, H=64, W=64] fp32     (128 MiB, read once)
// dw: [C=256, 1, 2, 2] fp32                  (cache-resident)
// out:[B, C, G, 128, 128] fp32               (512 MiB, written once)
//
// R8/R9 showed an achieved-HBM plateau at ~6.24 TB/s (78%) with STG streams,
// all on-chip units idle. This round: stage each block's contiguous 32 KB
// output tile in SMEM and emit it as ONE cp.async.bulk (TMA bulk store),
// so the write stream reaches L2/DRAM as large sequential bursts instead of
// interleaved 128 B lines from ~56 warps/SM.
//
// Block = 256 threads -> 64 output rows of one plane-half = 2048 float4 = 32 KB.
// Thread (lane q, row-group rg) computes 8 output rows at quad q:
//   4x LDG.64 (256 B/warp contiguous) + 8x STS.128 (conflict-free).

__global__ void __launch_bounds__(256)
DepthwiseRREUp_40106404610493_kernel(const float2* __restrict__ x2,
                                     const float4* __restrict__ dw4,  // [C] of (a,b,c,d)
                                     float4* __restrict__ out4) {
    __shared__ float4 tile[2048];   // 32 KB output staging

    int tid   = threadIdx.x;
    int b     = blockIdx.x;
    int plane = b >> 1;           // linear (b,c,g)
    int half  = b & 1;            // which 64-row half of the 128-row plane
    int g     = plane & 3;        // block-uniform
    int c     = (plane >> 2) & 255;

    int q        = tid & 31;      // quad within output row == lane
    int oi_local = (tid >> 5) << 3;       // local output row 0..56, step 8
    int oi0      = (half << 6) + oi_local;

    // Input rows oi0/2 .. oi0/2+3. Input plane = 2048 float2, 32 per row.
    const float2* xp = x2 + plane * 2048 + (oi0 >> 1) * 32 + q;
    float2 x0 = __ldcs(xp);
    float2 x1 = __ldcs(xp + 32);
    float2 x2v = __ldcs(xp + 64);
    float2 x3 = __ldcs(xp + 96);

    float4 w = dw4[c];  // a=w.x b=w.y c=w.z d=w.w (row-major 2x2)

    // numpy rot90 (CCW) k=g of [[a,b],[c,d]]:
    //   g=0: a b / c d    g=1: b d / a c
    //   g=2: d c / b a    g=3: c a / d b
    float f00, f01, f10, f11;
    switch (g) {
        case 0:  f00 = w.x; f01 = w.y; f10 = w.z; f11 = w.w; break;
        case 1:  f00 = w.y; f01 = w.w; f10 = w.x; f11 = w.z; break;
        case 2:  f00 = w.w; f01 = w.z; f10 = w.y; f11 = w.x; break;
        default: f00 = w.z; f01 = w.x; f10 = w.w; f11 = w.y; break;
    }

    // Stage 8 output rows into SMEM (row stride = 32 quads).
    float4* tp = tile + oi_local * 32 + q;
    tp[0]   = make_float4(x0.x * f00, x0.x * f01, x0.y * f00, x0.y * f01);
    tp[32]  = make_float4(x0.x * f10, x0.x * f11, x0.y * f10, x0.y * f11);
    tp[64]  = make_float4(x1.x * f00, x1.x * f01, x1.y * f00, x1.y * f01);
    tp[96]  = make_float4(x1.x * f10, x1.x * f11, x1.y * f10, x1.y * f11);
    tp[128] = make_float4(x2v.x * f00, x2v.x * f01, x2v.y * f00, x2v.y * f01);
    tp[160] = make_float4(x2v.x * f10, x2v.x * f11, x2v.y * f10, x2v.y * f11);
    tp[192] = make_float4(x3.x * f00, x3.x * f01, x3.y * f00, x3.y * f01);
    tp[224] = make_float4(x3.x * f10, x3.x * f11, x3.y * f10, x3.y * f11);

    __syncthreads();

    // One bulk store for the whole 32 KB tile.
    if (tid == 0) {
        uint32_t saddr;
        asm volatile("{ .reg .u64 t; cvta.to.shared.u64 t, %1; cvt.u32.u64 %0, t; }"
                     : "=r"(saddr) : "l"(tile));
        const float4* gdst = out4 + (size_t)b * 2048;
        asm volatile("fence.proxy.async.shared::cta;" ::: "memory");
        asm volatile("cp.async.bulk.global.shared::cta.bulk_group [%0], [%1], %2;"
                     :: "l"(gdst), "r"(saddr), "r"(32768) : "memory");
        asm volatile("cp.async.bulk.commit_group;" ::: "memory");
        asm volatile("cp.async.bulk.wait_group 0;" ::: "memory");
    }
}

extern "C" void kernel_launch(void* const* d_in, const int* in_sizes, int n_in,
                              void* d_out, int out_size) {
    const float2* x2  = (const float2*)d_in[0];
    const float4* dw4 = (const float4*)d_in[1];
    float4* out4      = (float4*)d_out;

    int blocks = out_size / 4 / 2048;             // 16384 blocks (32 KB out each)
    DepthwiseRREUp_40106404610493_kernel<<<blocks, 256>>>(x2, dw4, out4);
}